// round 3
// baseline (speedup 1.0000x reference)
#include <cuda_runtime.h>
#include <cuda_bf16.h>
#include <cstdint>

#define C_CLASSES 50000
#define C_PAD     50176            // 392 * 128
#define B_N       512
#define D_DIM     128
#define K2F       46.166241308446828f   // 32 * log2(e)
#define MRGF      0.1f

// ---------------- device scratch (static, no runtime alloc) ----------------
__device__ __align__(16) float          g_Xn[B_N * D_DIM];
__device__ __align__(16) __nv_bfloat16  g_Xn_bf[B_N * D_DIM];
__device__ __align__(16) __nv_bfloat16  g_Pn_bf[C_PAD * D_DIM];   // ~12.8 MB
__device__ float g_center_sim[C_CLASSES];
__device__ float g_cterm[C_PAD];
__device__ float g_Nbuf[C_PAD];
__device__ float g_Pbuf[C_CLASSES];
__device__ float g_acc[4];      // [0]=posAcc, [1]=negAcc, [2]=absAcc
__device__ int   g_num_valid;

__device__ __forceinline__ float ex2f(float x) {
    float y;
    asm("ex2.approx.ftz.f32 %0, %1;" : "=f"(y) : "f"(x));
    return y;
}

__device__ __forceinline__ float wred(float v) {
#pragma unroll
    for (int o = 16; o; o >>= 1) v += __shfl_xor_sync(0xffffffffu, v, o);
    return v;
}

// ---------------- kernel Z: zero accumulators + per-class sums -------------
__global__ void k_zero() {
    int i = blockIdx.x * 256 + threadIdx.x;
    if (i < C_PAD)     g_Nbuf[i] = 0.f;
    if (i < C_CLASSES) g_Pbuf[i] = 0.f;
    if (i < 4)         g_acc[i]  = 0.f;
    if (i == 0)        g_num_valid = 0;
}

// ---------------- kernel X: normalize X ------------------------------------
__global__ void k_xnorm(const float* __restrict__ X) {
    int row = blockIdx.x, d = threadIdx.x;     // 512 blocks x 128 threads
    __shared__ float sp[4];
    float x = X[row * D_DIM + d];
    float v = wred(x * x);
    if ((d & 31) == 0) sp[d >> 5] = v;
    __syncthreads();
    float ss = sp[0] + sp[1] + sp[2] + sp[3] + 1e-12f;
    float y = x / sqrtf(ss);
    g_Xn[row * D_DIM + d]    = y;
    g_Xn_bf[row * D_DIM + d] = __float2bfloat16(y);
}

// ---------------- kernel P: normalize proxies -> bf16, center_sim, |centers|
__global__ void k_pnorm(const float* __restrict__ proxies,
                        const float* __restrict__ centers) {
    int warp = threadIdx.x >> 5, lane = threadIdx.x & 31;
    int r = blockIdx.x * 8 + warp;
    if (r >= C_PAD) return;
    if (r < C_CLASSES) {
        const float* pr = proxies + (size_t)r * D_DIM;
        const float* cr = centers + (size_t)r * D_DIM;
        float p0 = pr[lane], p1 = pr[lane + 32], p2 = pr[lane + 64], p3 = pr[lane + 96];
        float ss = wred(p0 * p0 + p1 * p1 + p2 * p2 + p3 * p3);
        float inv = 1.0f / sqrtf(ss + 1e-12f);
        float n0 = p0 * inv, n1 = p1 * inv, n2 = p2 * inv, n3 = p3 * inv;
        __nv_bfloat16* dst = g_Pn_bf + (size_t)r * D_DIM;
        dst[lane]      = __float2bfloat16(n0);
        dst[lane + 32] = __float2bfloat16(n1);
        dst[lane + 64] = __float2bfloat16(n2);
        dst[lane + 96] = __float2bfloat16(n3);
        float c0 = cr[lane], c1 = cr[lane + 32], c2 = cr[lane + 64], c3 = cr[lane + 96];
        float dot = wred(n0 * c0 + n1 * c1 + n2 * c2 + n3 * c3);
        float cs2 = wred(c0 * c0 + c1 * c1 + c2 * c2 + c3 * c3);
        float ab  = wred(fabsf(c0) + fabsf(c1) + fabsf(c2) + fabsf(c3));
        if (lane == 0) {
            float pn2   = ss * inv * inv;
            float pnorm = fmaxf(sqrtf(pn2), 1e-8f);
            float cnorm = fmaxf(sqrtf(cs2), 1e-8f);
            g_center_sim[r] = dot / (pnorm * cnorm);
            g_cterm[r] = K2F * MRGF;                 // default: adj = 0
            atomicAdd(&g_acc[2], ab);
        }
    } else {
        __nv_bfloat16* dst = g_Pn_bf + (size_t)r * D_DIM;
        __nv_bfloat16 z = __float2bfloat16(0.f);
        dst[lane] = z; dst[lane + 32] = z; dst[lane + 64] = z; dst[lane + 96] = z;
        if (lane == 0) g_cterm[r] = K2F * MRGF;
    }
}

// ---------------- kernel S: per-class stats -> cterm for touched classes ---
__global__ void k_stats(const int* __restrict__ T) {
    __shared__ int   Ts[B_N];
    __shared__ float red[4];
    int b = blockIdx.x, d = threadIdx.x;       // 512 blocks x 128 threads
    for (int i = d; i < B_N; i += 128) Ts[i] = T[i];
    __syncthreads();
    int c = Ts[b];
    int dup = 0;
    for (int i = d; i < b; i += 128) if (Ts[i] == c) dup = 1;
    if (__syncthreads_or(dup)) return;         // only the representative block works
    float s = 0.f, s2 = 0.f, n = 0.f;
    for (int i = 0; i < B_N; i++) {
        if (Ts[i] == c) {
            float x = g_Xn[i * D_DIM + d];
            s += x; s2 += x * x; n += 1.f;
        }
    }
    float mean = s / n;
    float var  = s2 / n - mean * mean;
    var = fminf(fmaxf(var, 1e-6f), 10.0f);
    float v = wred(var);
    if ((d & 31) == 0) red[d >> 5] = v;
    __syncthreads();
    if (d == 0) {
        float vmean = (red[0] + red[1] + red[2] + red[3]) * (1.0f / 128.0f);
        float vw  = 1.0f / (1.0f + vmean);
        float adj = g_center_sim[c] * vw * 0.15f;
        g_cterm[c] = K2F * (MRGF + adj);
        atomicAdd(&g_num_valid, 1);
    }
}

// ---------------- kernel G: bf16 MMA GEMM fused with exp-sum ---------------
// Block: 256 threads (8 warps). Tile: 128 classes x 256 b-rows.
// Warp: 16 classes (two n8 tiles), full k=128 (8 k16 steps) in registers.
__global__ __launch_bounds__(256) void k_gemm() {
    extern __shared__ __align__(16) unsigned char smem_raw[];
    __nv_bfloat16* sA = reinterpret_cast<__nv_bfloat16*>(smem_raw);  // [256][136]

    const int tile  = blockIdx.x >> 1;
    const int mbase = (blockIdx.x & 1) * 256;

    // stage A half (256 x 128 bf16) with 272B row stride (conflict-free ldmatrix)
    for (int i = threadIdx.x; i < 256 * 16; i += 256) {
        int r = i >> 4, kc = i & 15;
        uint4 v = *reinterpret_cast<const uint4*>(g_Xn_bf + (mbase + r) * D_DIM + kc * 8);
        *reinterpret_cast<uint4*>(sA + r * 136 + kc * 8) = v;
    }
    __syncthreads();

    const int warp = threadIdx.x >> 5, lane = threadIdx.x & 31;
    const int tg = lane & 3, g = lane >> 2;
    const int cbase = tile * 128 + warp * 16;

    // B fragments for 16 classes x full K, resident in registers
    unsigned br[2][8][2];
#pragma unroll
    for (int t = 0; t < 2; t++) {
        const __nv_bfloat16* rowp = g_Pn_bf + (size_t)(cbase + t * 8 + g) * D_DIM;
#pragma unroll
        for (int ks = 0; ks < 8; ks++) {
            br[t][ks][0] = *reinterpret_cast<const unsigned*>(rowp + ks * 16 + tg * 2);
            br[t][ks][1] = *reinterpret_cast<const unsigned*>(rowp + ks * 16 + 8 + tg * 2);
        }
    }
    float ct[2][2], ns[2][2];
#pragma unroll
    for (int t = 0; t < 2; t++)
#pragma unroll
        for (int j = 0; j < 2; j++) {
            ct[t][j] = g_cterm[cbase + t * 8 + tg * 2 + j];
            ns[t][j] = 0.f;
        }

    unsigned sbase = (unsigned)__cvta_generic_to_shared(sA);
    const int sub = lane >> 3, rl = lane & 7;
    const int row_off = rl + ((sub & 1) << 3);
    const int k_off   = (sub >> 1) << 3;

    for (int m = 0; m < 256; m += 16) {
        float acc[2][4] = {};
#pragma unroll
        for (int ks = 0; ks < 8; ks++) {
            unsigned a0, a1, a2, a3;
            unsigned addr = sbase + (unsigned)(((m + row_off) * 136 + ks * 16 + k_off) * 2);
            asm volatile("ldmatrix.sync.aligned.m8n8.x4.shared.b16 {%0,%1,%2,%3}, [%4];"
                         : "=r"(a0), "=r"(a1), "=r"(a2), "=r"(a3) : "r"(addr));
#pragma unroll
            for (int t = 0; t < 2; t++) {
                asm volatile("mma.sync.aligned.m16n8k16.row.col.f32.bf16.bf16.f32 "
                             "{%0,%1,%2,%3}, {%4,%5,%6,%7}, {%8,%9}, {%0,%1,%2,%3};"
                             : "+f"(acc[t][0]), "+f"(acc[t][1]), "+f"(acc[t][2]), "+f"(acc[t][3])
                             : "r"(a0), "r"(a1), "r"(a2), "r"(a3),
                               "r"(br[t][ks][0]), "r"(br[t][ks][1]));
            }
        }
        // epilogue: exp(K2*cos + cterm) accumulated per class column
#pragma unroll
        for (int t = 0; t < 2; t++) {
            ns[t][0] += ex2f(fmaf(acc[t][0], K2F, ct[t][0])) +
                        ex2f(fmaf(acc[t][2], K2F, ct[t][0]));
            ns[t][1] += ex2f(fmaf(acc[t][1], K2F, ct[t][1])) +
                        ex2f(fmaf(acc[t][3], K2F, ct[t][1]));
        }
    }
    // reduce over the 8 row-groups (lanes xor 4,8,16)
#pragma unroll
    for (int o = 4; o < 32; o <<= 1)
#pragma unroll
        for (int t = 0; t < 2; t++)
#pragma unroll
            for (int j = 0; j < 2; j++)
                ns[t][j] += __shfl_xor_sync(0xffffffffu, ns[t][j], o);

    if (g == 0) {
#pragma unroll
        for (int t = 0; t < 2; t++)
#pragma unroll
            for (int j = 0; j < 2; j++) {
                int cls = cbase + t * 8 + tg * 2 + j;
                if (cls < C_CLASSES) atomicAdd(&g_Nbuf[cls], ns[t][j]);
            }
    }
}

// ---------------- kernel Q: one-hot pos terms + neg correction (fp32) ------
__global__ void k_pos(const int* __restrict__ T, const float* __restrict__ proxies) {
    int b = blockIdx.x, d = threadIdx.x;   // 512 blocks x 128 threads
    __shared__ float s1[4], s2[4];
    int c = T[b];
    const float* pr = proxies + (size_t)c * D_DIM;
    float p = pr[d];
    float v = wred(p * p);
    if ((d & 31) == 0) s1[d >> 5] = v;
    __syncthreads();
    float ss  = s1[0] + s1[1] + s1[2] + s1[3];
    float inv = 1.0f / sqrtf(ss + 1e-12f);
    float x = g_Xn[b * D_DIM + d];
    float v2 = wred(x * (p * inv));
    if ((d & 31) == 0) s2[d >> 5] = v2;
    __syncthreads();
    if (d == 0) {
        float cosv = s2[0] + s2[1] + s2[2] + s2[3];
        float base = fmaf(cosv, K2F, g_cterm[c]);          // K2*(comb + mrg)
        float nege = ex2f(base);
        float pose = ex2f(2.0f * K2F * MRGF - base);       // K2*(mrg - comb)
        atomicAdd(&g_Nbuf[c], -nege);
        atomicAdd(&g_Pbuf[c], pose);
    }
}

// ---------------- kernel R: sum log1p over classes --------------------------
__global__ void k_reduce() {
    int i = blockIdx.x * 256 + threadIdx.x;
    float nl = 0.f, pl = 0.f;
    if (i < C_CLASSES) {
        nl = log1pf(fmaxf(g_Nbuf[i], 0.f));
        pl = log1pf(fmaxf(g_Pbuf[i], 0.f));
    }
    __shared__ float sn[8], sp[8];
    float a  = wred(nl);
    float b2 = wred(pl);
    int w = threadIdx.x >> 5, l = threadIdx.x & 31;
    if (l == 0) { sn[w] = a; sp[w] = b2; }
    __syncthreads();
    if (threadIdx.x == 0) {
        float tn = 0.f, tp = 0.f;
#pragma unroll
        for (int k = 0; k < 8; k++) { tn += sn[k]; tp += sp[k]; }
        atomicAdd(&g_acc[1], tn);
        atomicAdd(&g_acc[0], tp);
    }
}

// ---------------- kernel F: combine ----------------------------------------
__global__ void k_final(float* __restrict__ out) {
    float pos = g_acc[0] / (float)g_num_valid;
    float neg = g_acc[1] * (1.0f / 50000.0f);
    float reg = g_acc[2] * (1.0f / (50000.0f * 128.0f));
    out[0] = pos + neg + 0.01f * reg;
}

// ---------------- launch ----------------------------------------------------
extern "C" void kernel_launch(void* const* d_in, const int* in_sizes, int n_in,
                              void* d_out, int out_size) {
    const float* X       = (const float*)d_in[0];
    const int*   T       = (const int*)d_in[1];
    const float* proxies = (const float*)d_in[2];
    const float* centers = (const float*)d_in[3];
    float* out = (float*)d_out;

    const int gemm_smem = 256 * 136 * 2;   // 69632 B dynamic smem
    cudaFuncSetAttribute(k_gemm, cudaFuncAttributeMaxDynamicSharedMemorySize, gemm_smem);

    k_zero <<<196, 256>>>();
    k_xnorm<<<512, 128>>>(X);
    k_pnorm<<<C_PAD / 8, 256>>>(proxies, centers);
    k_stats<<<512, 128>>>(T);
    k_gemm <<<784, 256, gemm_smem>>>();
    k_pos  <<<512, 128>>>(T, proxies);
    k_reduce<<<196, 256>>>();
    k_final<<<1, 1>>>(out);
}

// round 6
// speedup vs baseline: 1.0703x; 1.0703x over previous
#include <cuda_runtime.h>
#include <cuda_bf16.h>
#include <cstdint>

#define C_CLASSES 50000
#define C_PAD     50176            // 392 * 128
#define B_N       512
#define D_DIM     128
#define K2F       46.166241308446828f   // 32 * log2(e)
#define MRGF      0.1f

// ---------------- device scratch (static, no runtime alloc) ----------------
__device__ __align__(16) float          g_Xn[B_N * D_DIM];
__device__ __align__(16) __nv_bfloat16  g_Xn_bf[B_N * D_DIM];
__device__ __align__(16) __nv_bfloat16  g_Pn_bf[C_PAD * D_DIM];   // ~12.8 MB
__device__ float g_center_sim[C_CLASSES];
__device__ float g_cterm[C_PAD];     // K2 * (mrg + adj), log2 units
__device__ float g_Nbuf[C_PAD];      // UNSCALED: sum_b exp2(K2*cos) minus one-hot
__device__ float g_Pbuf[C_CLASSES];
__device__ float g_acc[4];           // [0]=posAcc, [1]=negAcc, [2]=absAcc
__device__ int   g_num_valid;
// slot-based per-class stats scratch (slot = first batch index of the class)
__device__ int   g_first[C_CLASSES];
__device__ float g_ssum[B_N * D_DIM];
__device__ float g_ssq [B_N * D_DIM];
__device__ int   g_scnt[B_N];

__device__ __forceinline__ float ex2f(float x) {
    float y;
    asm("ex2.approx.ftz.f32 %0, %1;" : "=f"(y) : "f"(x));
    return y;
}

__device__ __forceinline__ float wred(float v) {
#pragma unroll
    for (int o = 16; o; o >>= 1) v += __shfl_xor_sync(0xffffffffu, v, o);
    return v;
}

__device__ __forceinline__ unsigned smem_u32(const void* p) {
    unsigned a;
    asm("{ .reg .u64 t; cvta.to.shared.u64 t, %1; cvt.u32.u64 %0, t; }"
        : "=r"(a) : "l"(p));
    return a;
}

// ---------------- kernel Z: zero accumulators + scratch --------------------
__global__ void k_zero(const int* __restrict__ T) {
    int i = blockIdx.x * 256 + threadIdx.x;   // 256 blocks -> 65536 threads
    if (i < B_N * D_DIM) { g_ssum[i] = 0.f; g_ssq[i] = 0.f; }
    if (i < C_PAD)     g_Nbuf[i] = 0.f;
    if (i < C_CLASSES) g_Pbuf[i] = 0.f;
    if (i < B_N) {
        g_scnt[i] = 0;
        g_first[T[i]] = 0x7fffffff;   // init only touched classes
    }
    if (i < 4)  g_acc[i] = 0.f;
    if (i == 0) g_num_valid = 0;
}

// ---------------- kernel X: normalize X + first-occurrence map -------------
__global__ void k_xnorm(const float* __restrict__ X, const int* __restrict__ T) {
    int row = blockIdx.x, d = threadIdx.x;     // 512 blocks x 128 threads
    __shared__ float sp[4];
    float x = X[row * D_DIM + d];
    float v = wred(x * x);
    if ((d & 31) == 0) sp[d >> 5] = v;
    __syncthreads();
    float ss = sp[0] + sp[1] + sp[2] + sp[3] + 1e-12f;
    float y = x / sqrtf(ss);
    g_Xn[row * D_DIM + d]    = y;
    g_Xn_bf[row * D_DIM + d] = __float2bfloat16(y);
    if (d == 0) atomicMin(&g_first[T[row]], row);
}

// ---------------- kernel P: normalize proxies + center stats + class acc ---
__global__ void k_pnorm(const float* __restrict__ proxies,
                        const float* __restrict__ centers,
                        const int*   __restrict__ T) {
    int warp = threadIdx.x >> 5, lane = threadIdx.x & 31;
    int r = blockIdx.x * 8 + warp;
    if (r < C_CLASSES) {
        const float* pr = proxies + (size_t)r * D_DIM;
        const float* cr = centers + (size_t)r * D_DIM;
        float p0 = pr[lane], p1 = pr[lane + 32], p2 = pr[lane + 64], p3 = pr[lane + 96];
        float ss = wred(p0 * p0 + p1 * p1 + p2 * p2 + p3 * p3);
        float inv = 1.0f / sqrtf(ss + 1e-12f);
        float n0 = p0 * inv, n1 = p1 * inv, n2 = p2 * inv, n3 = p3 * inv;
        __nv_bfloat16* dst = g_Pn_bf + (size_t)r * D_DIM;
        dst[lane]      = __float2bfloat16(n0);
        dst[lane + 32] = __float2bfloat16(n1);
        dst[lane + 64] = __float2bfloat16(n2);
        dst[lane + 96] = __float2bfloat16(n3);
        float c0 = cr[lane], c1 = cr[lane + 32], c2 = cr[lane + 64], c3 = cr[lane + 96];
        float dot = wred(n0 * c0 + n1 * c1 + n2 * c2 + n3 * c3);
        float cs2 = wred(c0 * c0 + c1 * c1 + c2 * c2 + c3 * c3);
        float ab  = wred(fabsf(c0) + fabsf(c1) + fabsf(c2) + fabsf(c3));
        if (lane == 0) {
            float pn2   = ss * inv * inv;
            float pnorm = fmaxf(sqrtf(pn2), 1e-8f);
            float cnorm = fmaxf(sqrtf(cs2), 1e-8f);
            g_center_sim[r] = dot / (pnorm * cnorm);
            g_cterm[r] = K2F * MRGF;                 // default: adj = 0
            atomicAdd(&g_acc[2], ab);
        }
    } else if (r < C_PAD) {
        __nv_bfloat16* dst = g_Pn_bf + (size_t)r * D_DIM;
        __nv_bfloat16 z = __float2bfloat16(0.f);
        dst[lane] = z; dst[lane + 32] = z; dst[lane + 64] = z; dst[lane + 96] = z;
        if (lane == 0) g_cterm[r] = K2F * MRGF;
    }
    // embedded per-class accumulation: blocks 0..511 map to batch rows,
    // threads 0..127 map to dims (g_first/g_Xn are final after k_xnorm)
    if (blockIdx.x < B_N && threadIdx.x < D_DIM) {
        int b = blockIdx.x, d = threadIdx.x;
        int slot = g_first[T[b]];
        float x = g_Xn[b * D_DIM + d];
        atomicAdd(&g_ssum[slot * D_DIM + d], x);
        atomicAdd(&g_ssq [slot * D_DIM + d], x * x);
        if (d == 0) atomicAdd(&g_scnt[slot], 1);
    }
}

// ---------------- kernel G: mma.sync bf16 GEMM fused with exp2-sum ---------
// CTA tile: 256 classes x 128 batch rows, K=128. 8 warps, 32 classes each.
// A (batch rows) staged in smem (272B stride, conflict-free ldmatrix);
// B (class rows) resident in registers, loaded direct from L2.
// Accumulates UNSCALED sum_b exp2(K2*cos) into g_Nbuf (cterm applied later).
__global__ __launch_bounds__(256, 2) void k_gemm() {
    __shared__ __align__(16) __nv_bfloat16 sA[128 * 136];
    const int tid = threadIdx.x, wid = tid >> 5, lane = tid & 31;
    const int tile = blockIdx.x >> 2, quarter = blockIdx.x & 3;
    const int cbase = tile * 256 + wid * 32;
    const int mbase = quarter * 128;

    // stage A quarter (128 x 128 bf16) with padded stride
    for (int i = tid; i < 128 * 16; i += 256) {
        int r = i >> 4, q = i & 15;
        uint4 v = *reinterpret_cast<const uint4*>(g_Xn_bf + (mbase + r) * D_DIM + q * 8);
        *reinterpret_cast<uint4*>(sA + r * 136 + q * 8) = v;
    }

    const int tg = lane & 3, g = lane >> 2;

    // B fragments: 32 classes x full K=128, register resident
    unsigned br[4][8][2];
#pragma unroll
    for (int t = 0; t < 4; t++) {
        const __nv_bfloat16* rowp = g_Pn_bf + (size_t)(cbase + t * 8 + g) * D_DIM;
#pragma unroll
        for (int ks = 0; ks < 8; ks++) {
            br[t][ks][0] = *reinterpret_cast<const unsigned*>(rowp + ks * 16 + tg * 2);
            br[t][ks][1] = *reinterpret_cast<const unsigned*>(rowp + ks * 16 + 8 + tg * 2);
        }
    }
    float ns[4][2] = {};
    __syncthreads();

    const unsigned sbase = smem_u32(sA);
    const int sub = lane >> 3, rl = lane & 7;
    const int row_off = rl + ((sub & 1) << 3);
    const int k_off   = (sub >> 1) << 3;

    for (int m = 0; m < 128; m += 16) {
        float acc[4][4] = {};
#pragma unroll
        for (int ks = 0; ks < 8; ks++) {
            unsigned a0, a1, a2, a3;
            unsigned addr = sbase + (unsigned)(((m + row_off) * 136 + ks * 16 + k_off) * 2);
            asm volatile("ldmatrix.sync.aligned.m8n8.x4.shared.b16 {%0,%1,%2,%3}, [%4];"
                         : "=r"(a0), "=r"(a1), "=r"(a2), "=r"(a3) : "r"(addr));
#pragma unroll
            for (int t = 0; t < 4; t++) {
                asm volatile("mma.sync.aligned.m16n8k16.row.col.f32.bf16.bf16.f32 "
                             "{%0,%1,%2,%3}, {%4,%5,%6,%7}, {%8,%9}, {%0,%1,%2,%3};"
                             : "+f"(acc[t][0]), "+f"(acc[t][1]), "+f"(acc[t][2]), "+f"(acc[t][3])
                             : "r"(a0), "r"(a1), "r"(a2), "r"(a3),
                               "r"(br[t][ks][0]), "r"(br[t][ks][1]));
            }
        }
#pragma unroll
        for (int t = 0; t < 4; t++) {
            ns[t][0] += ex2f(acc[t][0] * K2F) + ex2f(acc[t][2] * K2F);
            ns[t][1] += ex2f(acc[t][1] * K2F) + ex2f(acc[t][3] * K2F);
        }
    }
    // reduce over the 8 row-groups (lanes xor 4,8,16)
#pragma unroll
    for (int o = 4; o < 32; o <<= 1)
#pragma unroll
        for (int t = 0; t < 4; t++)
#pragma unroll
            for (int j = 0; j < 2; j++)
                ns[t][j] += __shfl_xor_sync(0xffffffffu, ns[t][j], o);

    if (g == 0) {
#pragma unroll
        for (int t = 0; t < 4; t++)
#pragma unroll
            for (int j = 0; j < 2; j++)
                atomicAdd(&g_Nbuf[cbase + t * 8 + tg * 2 + j], ns[t][j]);
    }
}

// ---------------- kernel S: finalize per-class stats -> cterm --------------
__global__ void k_sfin(const int* __restrict__ T) {
    __shared__ float red[4];
    int b = blockIdx.x, d = threadIdx.x;       // 512 blocks x 128 threads
    int c = T[b];
    if (g_first[c] != b) return;               // uniform across block
    float n  = (float)g_scnt[b];
    float s  = g_ssum[b * D_DIM + d];
    float s2 = g_ssq [b * D_DIM + d];
    float mean = s / n;
    float var  = s2 / n - mean * mean;
    var = fminf(fmaxf(var, 1e-6f), 10.0f);
    float v = wred(var);
    if ((d & 31) == 0) red[d >> 5] = v;
    __syncthreads();
    if (d == 0) {
        float vmean = (red[0] + red[1] + red[2] + red[3]) * (1.0f / 128.0f);
        float vw  = 1.0f / (1.0f + vmean);
        float adj = g_center_sim[c] * vw * 0.15f;
        g_cterm[c] = K2F * (MRGF + adj);
        atomicAdd(&g_num_valid, 1);
    }
}

// ---------------- kernel Q: one-hot pos terms + neg correction (fp32) ------
__global__ void k_pos(const int* __restrict__ T, const float* __restrict__ proxies) {
    int b = blockIdx.x, d = threadIdx.x;   // 512 blocks x 128 threads
    __shared__ float s1[4], s2[4];
    int c = T[b];
    const float* pr = proxies + (size_t)c * D_DIM;
    float p = pr[d];
    float v = wred(p * p);
    if ((d & 31) == 0) s1[d >> 5] = v;
    __syncthreads();
    float ss  = s1[0] + s1[1] + s1[2] + s1[3];
    float inv = 1.0f / sqrtf(ss + 1e-12f);
    float x = g_Xn[b * D_DIM + d];
    float v2 = wred(x * (p * inv));
    if ((d & 31) == 0) s2[d >> 5] = v2;
    __syncthreads();
    if (d == 0) {
        float cosv = s2[0] + s2[1] + s2[2] + s2[3];
        // Nbuf is UNSCALED exp2(K2*cos): subtract one-hot term unscaled
        atomicAdd(&g_Nbuf[c], -ex2f(K2F * cosv));
        // pos term: exp(alpha*(mrg - combined)) in log2 units
        float base = fmaf(cosv, K2F, g_cterm[c]);
        atomicAdd(&g_Pbuf[c], ex2f(2.0f * K2F * MRGF - base));
    }
}

// ---------------- kernel R: apply cterm scale + sum log1p ------------------
__global__ void k_reduce() {
    int i = blockIdx.x * 256 + threadIdx.x;
    float nl = 0.f, pl = 0.f;
    if (i < C_CLASSES) {
        float scale = ex2f(g_cterm[i]);                 // e^{alpha*(mrg+adj)}
        nl = log1pf(fmaxf(scale * g_Nbuf[i], 0.f));
        pl = log1pf(fmaxf(g_Pbuf[i], 0.f));
    }
    __shared__ float sn[8], sp[8];
    float a  = wred(nl);
    float b2 = wred(pl);
    int w = threadIdx.x >> 5, l = threadIdx.x & 31;
    if (l == 0) { sn[w] = a; sp[w] = b2; }
    __syncthreads();
    if (threadIdx.x == 0) {
        float tn = 0.f, tp = 0.f;
#pragma unroll
        for (int k = 0; k < 8; k++) { tn += sn[k]; tp += sp[k]; }
        atomicAdd(&g_acc[1], tn);
        atomicAdd(&g_acc[0], tp);
    }
}

// ---------------- kernel F: combine ----------------------------------------
__global__ void k_final(float* __restrict__ out) {
    float pos = g_acc[0] / (float)g_num_valid;
    float neg = g_acc[1] * (1.0f / 50000.0f);
    float reg = g_acc[2] * (1.0f / (50000.0f * 128.0f));
    out[0] = pos + neg + 0.01f * reg;
}

// ---------------- launch ----------------------------------------------------
// k_gemm is app-launch #4 so the harness's ncu window (-s 5 -c 1, which
// captured launch #4 = k_stats in R3) lands on it next profile.
extern "C" void kernel_launch(void* const* d_in, const int* in_sizes, int n_in,
                              void* d_out, int out_size) {
    const float* X       = (const float*)d_in[0];
    const int*   T       = (const int*)d_in[1];
    const float* proxies = (const float*)d_in[2];
    const float* centers = (const float*)d_in[3];
    float* out = (float*)d_out;

    k_zero  <<<256, 256>>>(T);
    k_xnorm <<<512, 128>>>(X, T);
    k_pnorm <<<C_PAD / 8, 256>>>(proxies, centers, T);
    k_gemm  <<<784, 256>>>();            // no cterm dependency (factored out)
    k_sfin  <<<512, 128>>>(T);
    k_pos   <<<512, 128>>>(T, proxies);
    k_reduce<<<196, 256>>>();
    k_final <<<1, 1>>>(out);
}